// round 16
// baseline (speedup 1.0000x reference)
#include <cuda_runtime.h>
#include <cuda_bf16.h>
#include <cstdint>
#include <cstddef>

// ---------------------------------------------------------------------------
// ReLU-LSTM: S=2048, B=128, H=256, IN=256, L=2; one (h,c) state threads
// through both layers and time.
//
//  setup_kernel:  W0 -> pre-swizzled bf16 hi/lo image, h0 -> g_img[0],
//                 barrier reset.
//  xconv_kernel:  x -> global bf16 hi/lo images (split-bf16).
//  pro_main:      persistent 144-CTA HMMA GEMM for P (W in regs, cp.async
//                 double buffering).  (unchanged from R15)
//  lstm_kernel:   persistent 128 CTA x 512 thr. R16: active-group-only
//                 critical path (named barriers, 256-thread groups),
//                 hi/lo cp.async pipelining.
// ---------------------------------------------------------------------------

#define S_    2048
#define B_    128
#define H_    256
#define IN_   256
#define GH_   1024
#define NCTA  128
#define NTHR  512

#define OUT_Y  ((size_t)S_ * B_ * H_)
#define HY_OFF (OUT_Y)
#define CY_OFF (OUT_Y + 2ull * B_ * H_)

// lstm SMEM map (bytes)
#define OFF_A    0          // A tile: hi 8192 + lo 8192
#define OFF_WST  16384      // W staging (64 rows x 512B)
#define OFF_C    49152      // c-state: 16x17+ floats
#define LSTM_SMEM 50688

// prologue SMEM: two A buffers of 64KB (hi 32K + lo 32K); W staged in buf1.
#define PBUF_B   65536
#define PRO_SMEM 131072

typedef unsigned long long ull;

__device__ float g_P[(size_t)S_ * B_ * GH_];
__device__ __align__(16) unsigned char g_img[2][8][2][8192];  // [buf][bt][hi|lo]
__device__ __align__(16) unsigned char g_w0[16][2][32768];    // [ht][hi|lo] swizzled
__device__ __nv_bfloat16 g_xhi[(size_t)S_ * B_ * IN_];
__device__ __nv_bfloat16 g_xlo[(size_t)S_ * B_ * IN_];
__device__ unsigned g_bars[8][64];

__device__ __forceinline__ float sigf(float x) {
  float e = __expf(-x);
  float d = 1.0f + e;
  float r;
  asm("rcp.approx.f32 %0, %1;" : "=f"(r) : "f"(d));
  return r;
}
__device__ __forceinline__ uint32_t s2u(const void* p) {
  uint32_t a;
  asm("{ .reg .u64 t; cvta.to.shared.u64 t, %1; cvt.u32.u64 %0, t; }"
      : "=r"(a) : "l"(p));
  return a;
}
// 16B-chunk XOR swizzle within 128B groups: chunk c of row r.
__device__ __forceinline__ int swz(int r, int c) {
  return (c & 24) | ((c ^ r) & 7);
}

#define LDSM_X4(r0, r1, r2, r3, addr)                                          \
  asm volatile("ldmatrix.sync.aligned.m8n8.x4.shared.b16 {%0,%1,%2,%3}, [%4];" \
               : "=r"(r0), "=r"(r1), "=r"(r2), "=r"(r3) : "r"(addr))

#define MMA_BF16(d, a0, a1, a2, a3, b0, b1)                                \
  asm volatile("mma.sync.aligned.m16n8k16.row.col.f32.bf16.bf16.f32 "      \
               "{%0,%1,%2,%3}, {%4,%5,%6,%7}, {%8,%9}, {%0,%1,%2,%3};"     \
               : "+f"(d[0]), "+f"(d[1]), "+f"(d[2]), "+f"(d[3])            \
               : "r"(a0), "r"(a1), "r"(a2), "r"(a3), "r"(b0), "r"(b1))

#define CP_ASYNC16(dst, src)                                               \
  asm volatile("cp.async.ca.shared.global [%0], [%1], 16;"                 \
               :: "r"(dst), "l"(src) : "memory")
#define CP_COMMIT() asm volatile("cp.async.commit_group;" ::: "memory")
#define CP_WAIT(N)  asm volatile("cp.async.wait_group %0;" :: "n"(N) : "memory")
#define BAR_SYNC(id, n) \
  asm volatile("bar.sync %0, %1;" :: "r"(id), "r"(n) : "memory")

// ---------------------------------------------------------------------------
// setup: W0 bf16 hi/lo swizzled image, h0 image, barrier reset.
// ---------------------------------------------------------------------------
__global__ void __launch_bounds__(256) setup_kernel(
    const float* __restrict__ h0, const float* __restrict__ w_ih) {
  int gtid = blockIdx.x * 256 + threadIdx.x;   // 16384 threads
  if (gtid < 8) g_bars[gtid][0] = 0u;
  for (int i = gtid; i < B_ * H_; i += 16384) {
    int b = i >> 8, h = i & 255;
    float v = h0[i];
    __nv_bfloat16 hb = __float2bfloat16(v);
    __nv_bfloat16 lb = __float2bfloat16(v - __bfloat162float(hb));
    *(__nv_bfloat16*)&g_img[0][b >> 4][0][(b & 15) * 512 + h * 2] = hb;
    *(__nv_bfloat16*)&g_img[0][b >> 4][1][(b & 15) * 512 + h * 2] = lb;
  }
  for (int widx = gtid; widx < 16 * 64 * 256; widx += 16384) {
    int ht = widx >> 14, n = (widx >> 8) & 63, k = widx & 255;
    int gcol = (n & 3) * 256 + ht * 16 + (n >> 2);
    float v = w_ih[(size_t)gcol * IN_ + k];
    __nv_bfloat16 hb = __float2bfloat16(v);
    __nv_bfloat16 lb = __float2bfloat16(v - __bfloat162float(hb));
    int off = n * 512 + swz(n, k >> 3) * 16 + (k & 7) * 2;
    *(__nv_bfloat16*)&g_w0[ht][0][off] = hb;
    *(__nv_bfloat16*)&g_w0[ht][1][off] = lb;
  }
}

// ---------------------------------------------------------------------------
// xconv: x fp32 -> bf16 hi/lo images.
// ---------------------------------------------------------------------------
__global__ void __launch_bounds__(512) xconv_kernel(const float* __restrict__ x) {
  size_t base = ((size_t)blockIdx.x * 512 + threadIdx.x) * 8;
  float4 v0 = __ldcs((const float4*)(x + base));
  float4 v1 = __ldcs((const float4*)(x + base + 4));
  float f[8] = {v0.x, v0.y, v0.z, v0.w, v1.x, v1.y, v1.z, v1.w};
  uint32_t hi[4], lo[4];
#pragma unroll
  for (int i = 0; i < 4; ++i) {
    __nv_bfloat16 hA = __float2bfloat16(f[2 * i]);
    __nv_bfloat16 hB = __float2bfloat16(f[2 * i + 1]);
    __nv_bfloat16 lA = __float2bfloat16(f[2 * i] - __bfloat162float(hA));
    __nv_bfloat16 lB = __float2bfloat16(f[2 * i + 1] - __bfloat162float(hB));
    hi[i] = (uint32_t)__bfloat16_as_ushort(hA) |
            ((uint32_t)__bfloat16_as_ushort(hB) << 16);
    lo[i] = (uint32_t)__bfloat16_as_ushort(lA) |
            ((uint32_t)__bfloat16_as_ushort(lB) << 16);
  }
  __stcs((uint4*)&g_xhi[base], make_uint4(hi[0], hi[1], hi[2], hi[3]));
  __stcs((uint4*)&g_xlo[base], make_uint4(lo[0], lo[1], lo[2], lo[3]));
}

// ---------------------------------------------------------------------------
// pro_main: persistent HMMA prologue (unchanged from R15).
// ---------------------------------------------------------------------------
__global__ void __launch_bounds__(256) pro_main(
    const float* __restrict__ b_ih, const float* __restrict__ b_hh) {
  extern __shared__ char psm[];
  const uint32_t sbase = s2u(psm);
  const int tid  = threadIdx.x;
  const int lane = tid & 31;
  const int wid  = tid >> 5;
  const int ht   = blockIdx.x;
  const int yid  = blockIdx.y;

#pragma unroll
  for (int i = 0; i < 16; ++i) {
    int idx = tid + i * 256;
    int p = idx >> 11, cid = idx & 2047;
    CP_ASYNC16(sbase + PBUF_B + p * 32768 + cid * 16, &g_w0[ht][p][cid * 16]);
  }
  CP_COMMIT();
  {
    int rb = yid;
#pragma unroll
    for (int i = 0; i < 16; ++i) {
      int idx = tid + i * 256;
      int p = idx >> 11, rem = idx & 2047;
      int r = rem >> 5, c = rem & 31;
      const __nv_bfloat16* xp = p ? g_xlo : g_xhi;
      CP_ASYNC16(sbase + p * 32768 + r * 512 + swz(r, c) * 16,
                 (const char*)xp + ((size_t)(rb * 64 + r)) * 512 + c * 16);
    }
    CP_COMMIT();
  }
  CP_WAIT(1);
  __syncthreads();

  uint32_t bH[8][4], bL[8][4];
  {
    const int rrow = wid * 8 + (lane & 7);
    const int bsel = (lane >> 3) & 3;
#pragma unroll
    for (int kp = 0; kp < 8; ++kp) {
      uint32_t aH = sbase + PBUF_B + rrow * 512 + swz(rrow, kp * 4 + bsel) * 16;
      LDSM_X4(bH[kp][0], bH[kp][1], bH[kp][2], bH[kp][3], aH);
      LDSM_X4(bL[kp][0], bL[kp][1], bL[kp][2], bL[kp][3], aH + 32768);
    }
  }
  __syncthreads();

  const int n0 = wid * 8 + (lane & 3) * 2;
  float bias0, bias1;
  {
    int gc0 = (n0 & 3) * 256 + ht * 16 + (n0 >> 2);
    int gc1 = ((n0 + 1) & 3) * 256 + ht * 16 + ((n0 + 1) >> 2);
    bias0 = b_ih[gc0] + b_hh[gc0];
    bias1 = b_ih[gc1] + b_hh[gc1];
  }

  {
    int rbn = yid + 9;
    int rbl = (rbn < 4096) ? rbn : 0;
#pragma unroll
    for (int i = 0; i < 16; ++i) {
      int idx = tid + i * 256;
      int p = idx >> 11, rem = idx & 2047;
      int r = rem >> 5, c = rem & 31;
      const __nv_bfloat16* xp = p ? g_xlo : g_xhi;
      CP_ASYNC16(sbase + PBUF_B + p * 32768 + r * 512 + swz(r, c) * 16,
                 (const char*)xp + ((size_t)(rbl * 64 + r)) * 512 + c * 16);
    }
    CP_COMMIT();
  }

  const int rA = lane & 15, eA = lane >> 4;
  int cur = 0;
#pragma unroll 1
  for (int rb = yid; rb < 4096; rb += 9) {
    CP_WAIT(1);
    __syncthreads();
    const uint32_t Abuf = sbase + cur * PBUF_B;
#pragma unroll
    for (int mt = 0; mt < 4; ++mt) {
      float d[4] = {0.f, 0.f, 0.f, 0.f};
      const uint32_t aRow = Abuf + (mt * 16 + rA) * 512;
#pragma unroll
      for (int kp = 0; kp < 8; ++kp) {
        uint32_t h0r, h1r, h2r, h3r, h4, h5, h6, h7;
        uint32_t l0, l1, l2, l3, l4, l5, l6, l7;
        uint32_t a0 = aRow + swz(rA, 4 * kp + eA) * 16;
        uint32_t a1 = aRow + swz(rA, 4 * kp + 2 + eA) * 16;
        LDSM_X4(h0r, h1r, h2r, h3r, a0);
        LDSM_X4(l0, l1, l2, l3, a0 + 32768);
        LDSM_X4(h4, h5, h6, h7, a1);
        LDSM_X4(l4, l5, l6, l7, a1 + 32768);
        MMA_BF16(d, h0r, h1r, h2r, h3r, bH[kp][0], bH[kp][1]);
        MMA_BF16(d, h0r, h1r, h2r, h3r, bL[kp][0], bL[kp][1]);
        MMA_BF16(d, l0, l1, l2, l3,     bH[kp][0], bH[kp][1]);
        MMA_BF16(d, h4, h5, h6, h7,     bH[kp][2], bH[kp][3]);
        MMA_BF16(d, h4, h5, h6, h7,     bL[kp][2], bL[kp][3]);
        MMA_BF16(d, l4, l5, l6, l7,     bH[kp][2], bH[kp][3]);
      }
      size_t row0 = (size_t)rb * 64 + mt * 16 + (lane >> 2);
      float2 s0 = make_float2(d[0] + bias0, d[1] + bias1);
      float2 s1 = make_float2(d[2] + bias0, d[3] + bias1);
      __stcs((float2*)&g_P[row0 * GH_ + ht * 64 + n0], s0);
      __stcs((float2*)&g_P[(row0 + 8) * GH_ + ht * 64 + n0], s1);
    }
    __syncthreads();
    {
      int rb2 = rb + 18;
      int rbl = (rb2 < 4096) ? rb2 : 0;
#pragma unroll
      for (int i = 0; i < 16; ++i) {
        int idx = tid + i * 256;
        int p = idx >> 11, rem = idx & 2047;
        int r = rem >> 5, c = rem & 31;
        const __nv_bfloat16* xp = p ? g_xlo : g_xhi;
        CP_ASYNC16(Abuf + p * 32768 + r * 512 + swz(r, c) * 16,
                   (const char*)xp + ((size_t)(rbl * 64 + r)) * 512 + c * 16);
      }
      CP_COMMIT();
    }
    cur ^= 1;
  }
  CP_WAIT(0);
}

// ---------------------------------------------------------------------------
// Persistent recurrent kernel: 128 CTAs (8 bt x 16 ht) x 512 threads.
// R16: named-barrier active-group critical path + hi/lo cp.async pipeline.
// Warp w: grp = w>>3 (layer), nsl = w&7 (n-slice).
// ---------------------------------------------------------------------------
__global__ void __launch_bounds__(NTHR, 1) lstm_kernel(
    const float* __restrict__ c0,
    const float* __restrict__ w_ih, const float* __restrict__ b_ih,
    const float* __restrict__ w_hh, const float* __restrict__ b_hh,
    float* __restrict__ out) {
  extern __shared__ char smemc[];
  float* sC = (float*)(smemc + OFF_C);
  const uint32_t sbase = s2u(smemc);

  const int tid  = threadIdx.x;
  const int lane = tid & 31;
  const int wid  = tid >> 5;
  const int bt   = blockIdx.x >> 4;
  const int ht   = blockIdx.x & 15;
  const int grp  = wid >> 3;
  const int nsl  = wid & 7;
  const int gbar = 8 + grp;          // named barrier id for this group
  const int tg   = tid & 255;        // thread index within group
  unsigned* ctr  = &g_bars[bt][0];

  // ---- stage W -> registers (validated R13 preamble) ----
  uint32_t bH[8][4], bL[8][4];
  {
    const int rrow = nsl * 8 + (lane & 7);
    const int bsel = (lane >> 3) & 3;
#pragma unroll 1
    for (int l = 0; l < 2; ++l) {
#pragma unroll 1
      for (int p = 0; p < 2; ++p) {
        for (int idx = tid; idx < 64 * 256; idx += NTHR) {
          int n = idx >> 8, k = idx & 255;
          int g = n & 3, hv = n >> 2;
          int gcol = g * 256 + ht * 16 + hv;
          float v;
          if (l == 0) v = w_hh[(size_t)gcol * H_ + k];
          else v = w_ih[(size_t)(GH_ + gcol) * IN_ + k] +
                   w_hh[(size_t)(GH_ + gcol) * H_ + k];
          __nv_bfloat16 hb = __float2bfloat16(v);
          __nv_bfloat16 sv = p == 0 ? hb
                           : __float2bfloat16(v - __bfloat162float(hb));
          int c = k >> 3;
          *(__nv_bfloat16*)(smemc + OFF_WST + n * 512 + swz(n, c) * 16 +
                            (k & 7) * 2) = sv;
        }
        __syncthreads();
        if (grp == l) {
#pragma unroll
          for (int kp = 0; kp < 8; ++kp) {
            int c = kp * 4 + bsel;
            uint32_t addr = sbase + OFF_WST + rrow * 512 + swz(rrow, c) * 16;
            if (p == 0) { LDSM_X4(bH[kp][0], bH[kp][1], bH[kp][2], bH[kp][3], addr); }
            else        { LDSM_X4(bL[kp][0], bL[kp][1], bL[kp][2], bL[kp][3], addr); }
          }
        }
        __syncthreads();
      }
    }
  }

  const int hv_c   = nsl * 2 + ((lane & 3) >> 1);
  const int bl_c   = (lane >> 2) + ((lane & 1) ? 8 : 0);
  const int bglob  = bt * 16 + bl_c;
  const int hglob  = ht * 16 + hv_c;
  float4 bias4 = make_float4(0.f, 0.f, 0.f, 0.f);
  if (grp == 1) {
#pragma unroll
    for (int g = 0; g < 4; ++g) {
      int gc = g * 256 + ht * 16 + hv_c;
      ((float*)&bias4)[g] = b_ih[GH_ + gc] + b_hh[GH_ + gc];
    }
  }
  if (tid < 256) sC[(tid >> 4) * 17 + (tid & 15)] =
      c0[(size_t)(bt * 16 + (tid >> 4)) * H_ + ht * 16 + (tid & 15)];
  __syncthreads();

  float4 pv = make_float4(0.f, 0.f, 0.f, 0.f);
  if (grp == 0)
    pv = __ldcs((const float4*)&g_P[(size_t)bglob * GH_ + ht * 64 + hv_c * 4]);

  const int rA = lane & 15, eA = lane >> 4;
  const uint32_t aRow = sbase + OFF_A + rA * 512;

#pragma unroll 1
  for (int q = 0; q < 2 * S_; ++q) {
    const int t  = q >> 1;
    const int ph = q & 1;

    if (grp == ph) {
      // ---- poll (one thread) + release group via named barrier ----
      if (tg == 0) {
        unsigned v;
        do {
          asm volatile("ld.acquire.gpu.b32 %0, [%1];" : "=r"(v) : "l"(ctr) : "memory");
        } while (v < (unsigned)q * 16);
      }
      BAR_SYNC(gbar, 256);

      // ---- stage A: hi group then lo group (pipelined) ----
#pragma unroll
      for (int ii = 0; ii < 2; ++ii) {      // hi chunks 0..511
        int idx = tg + ii * 256;
        int r = idx >> 5, c = idx & 31;
        CP_ASYNC16(sbase + OFF_A + r * 512 + swz(r, c) * 16,
                   &g_img[ph][bt][0][r * 512 + c * 16]);
      }
      CP_COMMIT();
#pragma unroll
      for (int ii = 0; ii < 2; ++ii) {      // lo chunks 0..511
        int idx = tg + ii * 256;
        int r = idx >> 5, c = idx & 31;
        CP_ASYNC16(sbase + OFF_A + 8192 + r * 512 + swz(r, c) * 16,
                   &g_img[ph][bt][1][r * 512 + c * 16]);
      }
      CP_COMMIT();

      CP_WAIT(1);                 // hi plane in SMEM (this thread's part)
      BAR_SYNC(gbar, 256);        // all hi chunks visible

      // ---- hi-fragment MMAs (32) while lo plane lands ----
      float d[4] = {0.f, 0.f, 0.f, 0.f};
#pragma unroll
      for (int kp = 0; kp < 8; ++kp) {
        uint32_t h0r, h1r, h2r, h3r, h4, h5, h6, h7;
        uint32_t a0 = aRow + swz(rA, 4 * kp + eA) * 16;
        uint32_t a1 = aRow + swz(rA, 4 * kp + 2 + eA) * 16;
        LDSM_X4(h0r, h1r, h2r, h3r, a0);
        LDSM_X4(h4, h5, h6, h7, a1);
        MMA_BF16(d, h0r, h1r, h2r, h3r, bH[kp][0], bH[kp][1]);
        MMA_BF16(d, h0r, h1r, h2r, h3r, bL[kp][0], bL[kp][1]);
        MMA_BF16(d, h4, h5, h6, h7,     bH[kp][2], bH[kp][3]);
        MMA_BF16(d, h4, h5, h6, h7,     bL[kp][2], bL[kp][3]);
      }
      CP_WAIT(0);                 // lo plane in SMEM (this thread's part)
      BAR_SYNC(gbar, 256);        // all lo chunks visible
#pragma unroll
      for (int kp = 0; kp < 8; ++kp) {
        uint32_t l0, l1, l2, l3, l4, l5, l6, l7;
        uint32_t a0 = aRow + swz(rA, 4 * kp + eA) * 16 + 8192;
        uint32_t a1 = aRow + swz(rA, 4 * kp + 2 + eA) * 16 + 8192;
        LDSM_X4(l0, l1, l2, l3, a0);
        LDSM_X4(l4, l5, l6, l7, a1);
        MMA_BF16(d, l0, l1, l2, l3, bH[kp][0], bH[kp][1]);
        MMA_BF16(d, l4, l5, l6, l7, bH[kp][2], bH[kp][3]);
      }

      // ---- register epilogue (validated) ----
      float e0 = __shfl_xor_sync(0xFFFFFFFFu, d[0], 1);
      float e1 = __shfl_xor_sync(0xFFFFFFFFu, d[1], 1);
      float e2 = __shfl_xor_sync(0xFFFFFFFFu, d[2], 1);
      float e3 = __shfl_xor_sync(0xFFFFFFFFu, d[3], 1);
      float gi, gf, gc, go;
      if (!(lane & 1)) { gi = d[0]; gf = d[1]; gc = e0; go = e1; }
      else             { gi = e2;   gf = e3;   gc = d[2]; go = d[3]; }
      float4 ab = (grp == 0) ? pv : bias4;
      gi += ab.x; gf += ab.y; gc += ab.z; go += ab.w;
      int ci = bl_c * 17 + hv_c;
      float cold = sC[ci];
      float cnew = sigf(gf) * cold + sigf(gi) * fmaxf(gc, 0.0f);
      float h = sigf(go) * fmaxf(cnew, 0.0f);
      sC[ci] = cnew;
      __nv_bfloat16 hb = __float2bfloat16(h);
      __nv_bfloat16 lb = __float2bfloat16(h - __bfloat162float(hb));
      *(__nv_bfloat16*)&g_img[ph ^ 1][bt][0][bl_c * 512 + hglob * 2] = hb;
      *(__nv_bfloat16*)&g_img[ph ^ 1][bt][1][bl_c * 512 + hglob * 2] = lb;
      if (t == S_ - 1) {
        size_t lo2 = (size_t)ph * B_ * H_ + (size_t)bglob * H_ + hglob;
        out[HY_OFF + lo2] = h;
        out[CY_OFF + lo2] = cnew;
      }
      // ---- arrival: group barrier (membar.cta) then one release-red ----
      BAR_SYNC(gbar, 256);
      if (tg == 0)
        asm volatile("red.release.gpu.global.add.u32 [%0], %1;"
                     :: "l"(ctr), "r"(1u) : "memory");
      // off-path work inside the barrier window
      if (ph) __stcs(&out[(size_t)t * B_ * H_ + (size_t)bglob * H_ + hglob], h);
    } else {
      // idle group: only P prefetch for next step during layer-1 phases
      if (grp == 0 && ph == 1 && t + 1 < S_)
        pv = __ldcs((const float4*)
                    &g_P[((size_t)(t + 1) * B_ + bglob) * GH_ + ht * 64 + hv_c * 4]);
    }
  }
}

extern "C" void kernel_launch(void* const* d_in, const int* in_sizes, int n_in,
                              void* d_out, int out_size) {
  const float* x    = (const float*)d_in[0];
  const float* h0   = (const float*)d_in[1];
  const float* c0   = (const float*)d_in[2];
  const float* w_ih = (const float*)d_in[3];
  const float* b_ih = (const float*)d_in[4];
  const float* w_hh = (const float*)d_in[5];
  const float* b_hh = (const float*)d_in[6];
  float* out = (float*)d_out;

  static bool attr_done = false;
  if (!attr_done) {
    cudaFuncSetAttribute(pro_main,
                         cudaFuncAttributeMaxDynamicSharedMemorySize, PRO_SMEM);
    cudaFuncSetAttribute(lstm_kernel,
                         cudaFuncAttributeMaxDynamicSharedMemorySize, LSTM_SMEM);
    attr_done = true;
  }

  setup_kernel<<<64, 256>>>(h0, w_ih);
  xconv_kernel<<<16384, 512>>>(x);
  pro_main<<<dim3(16, 9), 256, PRO_SMEM>>>(b_ih, b_hh);
  lstm_kernel<<<NCTA, NTHR, LSTM_SMEM>>>(c0, w_ih, b_ih, w_hh, b_hh, out);
}

// round 17
// speedup vs baseline: 1.0087x; 1.0087x over previous
#include <cuda_runtime.h>
#include <cuda_bf16.h>
#include <cstdint>
#include <cstddef>

// ---------------------------------------------------------------------------
// ReLU-LSTM: S=2048, B=128, H=256, IN=256, L=2; one (h,c) state threads
// through both layers and time.
//
//  setup_kernel:  W0 -> pre-swizzled bf16 hi/lo image, h0 -> g_img[0],
//                 barrier reset.
//  xconv_kernel:  x -> global bf16 hi/lo images (split-bf16).
//  pro_main:      persistent 144-CTA HMMA GEMM for P (W in regs, cp.async
//                 double buffering).  (unchanged from R15)
//  lstm_kernel:   R15 structure (CTA-wide syncs, all-thread staging) +
//                 hi/lo cp.async commit-group pipelining: hi MMAs run while
//                 the lo plane is still in flight.
// ---------------------------------------------------------------------------

#define S_    2048
#define B_    128
#define H_    256
#define IN_   256
#define GH_   1024
#define NCTA  128
#define NTHR  512

#define OUT_Y  ((size_t)S_ * B_ * H_)
#define HY_OFF (OUT_Y)
#define CY_OFF (OUT_Y + 2ull * B_ * H_)

// lstm SMEM map (bytes)
#define OFF_A    0          // A tile: hi 8192 + lo 8192
#define OFF_WST  16384      // W staging (64 rows x 512B)
#define OFF_C    49152      // c-state: 16x17+ floats
#define LSTM_SMEM 50688

// prologue SMEM: two A buffers of 64KB (hi 32K + lo 32K); W staged in buf1.
#define PBUF_B   65536
#define PRO_SMEM 131072

typedef unsigned long long ull;

__device__ float g_P[(size_t)S_ * B_ * GH_];
__device__ __align__(16) unsigned char g_img[2][8][2][8192];  // [buf][bt][hi|lo]
__device__ __align__(16) unsigned char g_w0[16][2][32768];    // [ht][hi|lo] swizzled
__device__ __nv_bfloat16 g_xhi[(size_t)S_ * B_ * IN_];
__device__ __nv_bfloat16 g_xlo[(size_t)S_ * B_ * IN_];
__device__ unsigned g_bars[8][64];

__device__ __forceinline__ float sigf(float x) {
  float e = __expf(-x);
  float d = 1.0f + e;
  float r;
  asm("rcp.approx.f32 %0, %1;" : "=f"(r) : "f"(d));
  return r;
}
__device__ __forceinline__ uint32_t s2u(const void* p) {
  uint32_t a;
  asm("{ .reg .u64 t; cvta.to.shared.u64 t, %1; cvt.u32.u64 %0, t; }"
      : "=r"(a) : "l"(p));
  return a;
}
// 16B-chunk XOR swizzle within 128B groups: chunk c of row r.
__device__ __forceinline__ int swz(int r, int c) {
  return (c & 24) | ((c ^ r) & 7);
}

#define LDSM_X4(r0, r1, r2, r3, addr)                                          \
  asm volatile("ldmatrix.sync.aligned.m8n8.x4.shared.b16 {%0,%1,%2,%3}, [%4];" \
               : "=r"(r0), "=r"(r1), "=r"(r2), "=r"(r3) : "r"(addr))

#define MMA_BF16(d, a0, a1, a2, a3, b0, b1)                                \
  asm volatile("mma.sync.aligned.m16n8k16.row.col.f32.bf16.bf16.f32 "      \
               "{%0,%1,%2,%3}, {%4,%5,%6,%7}, {%8,%9}, {%0,%1,%2,%3};"     \
               : "+f"(d[0]), "+f"(d[1]), "+f"(d[2]), "+f"(d[3])            \
               : "r"(a0), "r"(a1), "r"(a2), "r"(a3), "r"(b0), "r"(b1))

#define CP_ASYNC16(dst, src)                                               \
  asm volatile("cp.async.ca.shared.global [%0], [%1], 16;"                 \
               :: "r"(dst), "l"(src) : "memory")
#define CP_COMMIT() asm volatile("cp.async.commit_group;" ::: "memory")
#define CP_WAIT(N)  asm volatile("cp.async.wait_group %0;" :: "n"(N) : "memory")

// ---------------------------------------------------------------------------
// setup: W0 bf16 hi/lo swizzled image, h0 image, barrier reset.
// ---------------------------------------------------------------------------
__global__ void __launch_bounds__(256) setup_kernel(
    const float* __restrict__ h0, const float* __restrict__ w_ih) {
  int gtid = blockIdx.x * 256 + threadIdx.x;   // 16384 threads
  if (gtid < 8) g_bars[gtid][0] = 0u;
  for (int i = gtid; i < B_ * H_; i += 16384) {
    int b = i >> 8, h = i & 255;
    float v = h0[i];
    __nv_bfloat16 hb = __float2bfloat16(v);
    __nv_bfloat16 lb = __float2bfloat16(v - __bfloat162float(hb));
    *(__nv_bfloat16*)&g_img[0][b >> 4][0][(b & 15) * 512 + h * 2] = hb;
    *(__nv_bfloat16*)&g_img[0][b >> 4][1][(b & 15) * 512 + h * 2] = lb;
  }
  for (int widx = gtid; widx < 16 * 64 * 256; widx += 16384) {
    int ht = widx >> 14, n = (widx >> 8) & 63, k = widx & 255;
    int gcol = (n & 3) * 256 + ht * 16 + (n >> 2);
    float v = w_ih[(size_t)gcol * IN_ + k];
    __nv_bfloat16 hb = __float2bfloat16(v);
    __nv_bfloat16 lb = __float2bfloat16(v - __bfloat162float(hb));
    int off = n * 512 + swz(n, k >> 3) * 16 + (k & 7) * 2;
    *(__nv_bfloat16*)&g_w0[ht][0][off] = hb;
    *(__nv_bfloat16*)&g_w0[ht][1][off] = lb;
  }
}

// ---------------------------------------------------------------------------
// xconv: x fp32 -> bf16 hi/lo images.
// ---------------------------------------------------------------------------
__global__ void __launch_bounds__(512) xconv_kernel(const float* __restrict__ x) {
  size_t base = ((size_t)blockIdx.x * 512 + threadIdx.x) * 8;
  float4 v0 = __ldcs((const float4*)(x + base));
  float4 v1 = __ldcs((const float4*)(x + base + 4));
  float f[8] = {v0.x, v0.y, v0.z, v0.w, v1.x, v1.y, v1.z, v1.w};
  uint32_t hi[4], lo[4];
#pragma unroll
  for (int i = 0; i < 4; ++i) {
    __nv_bfloat16 hA = __float2bfloat16(f[2 * i]);
    __nv_bfloat16 hB = __float2bfloat16(f[2 * i + 1]);
    __nv_bfloat16 lA = __float2bfloat16(f[2 * i] - __bfloat162float(hA));
    __nv_bfloat16 lB = __float2bfloat16(f[2 * i + 1] - __bfloat162float(hB));
    hi[i] = (uint32_t)__bfloat16_as_ushort(hA) |
            ((uint32_t)__bfloat16_as_ushort(hB) << 16);
    lo[i] = (uint32_t)__bfloat16_as_ushort(lA) |
            ((uint32_t)__bfloat16_as_ushort(lB) << 16);
  }
  __stcs((uint4*)&g_xhi[base], make_uint4(hi[0], hi[1], hi[2], hi[3]));
  __stcs((uint4*)&g_xlo[base], make_uint4(lo[0], lo[1], lo[2], lo[3]));
}

// ---------------------------------------------------------------------------
// pro_main: persistent HMMA prologue (unchanged from R15).
// ---------------------------------------------------------------------------
__global__ void __launch_bounds__(256) pro_main(
    const float* __restrict__ b_ih, const float* __restrict__ b_hh) {
  extern __shared__ char psm[];
  const uint32_t sbase = s2u(psm);
  const int tid  = threadIdx.x;
  const int lane = tid & 31;
  const int wid  = tid >> 5;
  const int ht   = blockIdx.x;
  const int yid  = blockIdx.y;

#pragma unroll
  for (int i = 0; i < 16; ++i) {
    int idx = tid + i * 256;
    int p = idx >> 11, cid = idx & 2047;
    CP_ASYNC16(sbase + PBUF_B + p * 32768 + cid * 16, &g_w0[ht][p][cid * 16]);
  }
  CP_COMMIT();
  {
    int rb = yid;
#pragma unroll
    for (int i = 0; i < 16; ++i) {
      int idx = tid + i * 256;
      int p = idx >> 11, rem = idx & 2047;
      int r = rem >> 5, c = rem & 31;
      const __nv_bfloat16* xp = p ? g_xlo : g_xhi;
      CP_ASYNC16(sbase + p * 32768 + r * 512 + swz(r, c) * 16,
                 (const char*)xp + ((size_t)(rb * 64 + r)) * 512 + c * 16);
    }
    CP_COMMIT();
  }
  CP_WAIT(1);
  __syncthreads();

  uint32_t bH[8][4], bL[8][4];
  {
    const int rrow = wid * 8 + (lane & 7);
    const int bsel = (lane >> 3) & 3;
#pragma unroll
    for (int kp = 0; kp < 8; ++kp) {
      uint32_t aH = sbase + PBUF_B + rrow * 512 + swz(rrow, kp * 4 + bsel) * 16;
      LDSM_X4(bH[kp][0], bH[kp][1], bH[kp][2], bH[kp][3], aH);
      LDSM_X4(bL[kp][0], bL[kp][1], bL[kp][2], bL[kp][3], aH + 32768);
    }
  }
  __syncthreads();

  const int n0 = wid * 8 + (lane & 3) * 2;
  float bias0, bias1;
  {
    int gc0 = (n0 & 3) * 256 + ht * 16 + (n0 >> 2);
    int gc1 = ((n0 + 1) & 3) * 256 + ht * 16 + ((n0 + 1) >> 2);
    bias0 = b_ih[gc0] + b_hh[gc0];
    bias1 = b_ih[gc1] + b_hh[gc1];
  }

  {
    int rbn = yid + 9;
    int rbl = (rbn < 4096) ? rbn : 0;
#pragma unroll
    for (int i = 0; i < 16; ++i) {
      int idx = tid + i * 256;
      int p = idx >> 11, rem = idx & 2047;
      int r = rem >> 5, c = rem & 31;
      const __nv_bfloat16* xp = p ? g_xlo : g_xhi;
      CP_ASYNC16(sbase + PBUF_B + p * 32768 + r * 512 + swz(r, c) * 16,
                 (const char*)xp + ((size_t)(rbl * 64 + r)) * 512 + c * 16);
    }
    CP_COMMIT();
  }

  const int rA = lane & 15, eA = lane >> 4;
  int cur = 0;
#pragma unroll 1
  for (int rb = yid; rb < 4096; rb += 9) {
    CP_WAIT(1);
    __syncthreads();
    const uint32_t Abuf = sbase + cur * PBUF_B;
#pragma unroll
    for (int mt = 0; mt < 4; ++mt) {
      float d[4] = {0.f, 0.f, 0.f, 0.f};
      const uint32_t aRow = Abuf + (mt * 16 + rA) * 512;
#pragma unroll
      for (int kp = 0; kp < 8; ++kp) {
        uint32_t h0r, h1r, h2r, h3r, h4, h5, h6, h7;
        uint32_t l0, l1, l2, l3, l4, l5, l6, l7;
        uint32_t a0 = aRow + swz(rA, 4 * kp + eA) * 16;
        uint32_t a1 = aRow + swz(rA, 4 * kp + 2 + eA) * 16;
        LDSM_X4(h0r, h1r, h2r, h3r, a0);
        LDSM_X4(l0, l1, l2, l3, a0 + 32768);
        LDSM_X4(h4, h5, h6, h7, a1);
        LDSM_X4(l4, l5, l6, l7, a1 + 32768);
        MMA_BF16(d, h0r, h1r, h2r, h3r, bH[kp][0], bH[kp][1]);
        MMA_BF16(d, h0r, h1r, h2r, h3r, bL[kp][0], bL[kp][1]);
        MMA_BF16(d, l0, l1, l2, l3,     bH[kp][0], bH[kp][1]);
        MMA_BF16(d, h4, h5, h6, h7,     bH[kp][2], bH[kp][3]);
        MMA_BF16(d, h4, h5, h6, h7,     bL[kp][2], bL[kp][3]);
        MMA_BF16(d, l4, l5, l6, l7,     bH[kp][2], bH[kp][3]);
      }
      size_t row0 = (size_t)rb * 64 + mt * 16 + (lane >> 2);
      float2 s0 = make_float2(d[0] + bias0, d[1] + bias1);
      float2 s1 = make_float2(d[2] + bias0, d[3] + bias1);
      __stcs((float2*)&g_P[row0 * GH_ + ht * 64 + n0], s0);
      __stcs((float2*)&g_P[(row0 + 8) * GH_ + ht * 64 + n0], s1);
    }
    __syncthreads();
    {
      int rb2 = rb + 18;
      int rbl = (rb2 < 4096) ? rb2 : 0;
#pragma unroll
      for (int i = 0; i < 16; ++i) {
        int idx = tid + i * 256;
        int p = idx >> 11, rem = idx & 2047;
        int r = rem >> 5, c = rem & 31;
        const __nv_bfloat16* xp = p ? g_xlo : g_xhi;
        CP_ASYNC16(Abuf + p * 32768 + r * 512 + swz(r, c) * 16,
                   (const char*)xp + ((size_t)(rbl * 64 + r)) * 512 + c * 16);
      }
      CP_COMMIT();
    }
    cur ^= 1;
  }
  CP_WAIT(0);
}

// Per-bt 16-CTA barrier (R15-validated form).
__device__ __forceinline__ void bar_arrive(unsigned* ctr) {
  __syncthreads();
  if (threadIdx.x == 0) {
    asm volatile("red.release.gpu.global.add.u32 [%0], %1;"
                 :: "l"(ctr), "r"(1u) : "memory");
  }
}
__device__ __forceinline__ void bar_wait(unsigned* ctr, unsigned target) {
  if (threadIdx.x == 0) {
    unsigned v;
    do {
      asm volatile("ld.acquire.gpu.b32 %0, [%1];" : "=r"(v) : "l"(ctr) : "memory");
    } while (v < target);
  }
  __syncthreads();
}

// ---------------------------------------------------------------------------
// Persistent recurrent kernel: 128 CTAs (8 bt x 16 ht) x 512 threads.
// R17 = R15 + hi/lo commit-group pipelining (hi MMAs overlap lo staging).
// Warp w: grp = w>>3 (layer), nsl = w&7 (n-slice).
// ---------------------------------------------------------------------------
__global__ void __launch_bounds__(NTHR, 1) lstm_kernel(
    const float* __restrict__ c0,
    const float* __restrict__ w_ih, const float* __restrict__ b_ih,
    const float* __restrict__ w_hh, const float* __restrict__ b_hh,
    float* __restrict__ out) {
  extern __shared__ char smemc[];
  float* sC = (float*)(smemc + OFF_C);
  const uint32_t sbase = s2u(smemc);

  const int tid  = threadIdx.x;
  const int lane = tid & 31;
  const int wid  = tid >> 5;
  const int bt   = blockIdx.x >> 4;
  const int ht   = blockIdx.x & 15;
  const int grp  = wid >> 3;
  const int nsl  = wid & 7;
  unsigned* ctr  = &g_bars[bt][0];

  // ---- stage W -> registers (validated R13 preamble) ----
  uint32_t bH[8][4], bL[8][4];
  {
    const int rrow = nsl * 8 + (lane & 7);
    const int bsel = (lane >> 3) & 3;
#pragma unroll 1
    for (int l = 0; l < 2; ++l) {
#pragma unroll 1
      for (int p = 0; p < 2; ++p) {
        for (int idx = tid; idx < 64 * 256; idx += NTHR) {
          int n = idx >> 8, k = idx & 255;
          int g = n & 3, hv = n >> 2;
          int gcol = g * 256 + ht * 16 + hv;
          float v;
          if (l == 0) v = w_hh[(size_t)gcol * H_ + k];
          else v = w_ih[(size_t)(GH_ + gcol) * IN_ + k] +
                   w_hh[(size_t)(GH_ + gcol) * H_ + k];
          __nv_bfloat16 hb = __float2bfloat16(v);
          __nv_bfloat16 sv = p == 0 ? hb
                           : __float2bfloat16(v - __bfloat162float(hb));
          int c = k >> 3;
          *(__nv_bfloat16*)(smemc + OFF_WST + n * 512 + swz(n, c) * 16 +
                            (k & 7) * 2) = sv;
        }
        __syncthreads();
        if (grp == l) {
#pragma unroll
          for (int kp = 0; kp < 8; ++kp) {
            int c = kp * 4 + bsel;
            uint32_t addr = sbase + OFF_WST + rrow * 512 + swz(rrow, c) * 16;
            if (p == 0) { LDSM_X4(bH[kp][0], bH[kp][1], bH[kp][2], bH[kp][3], addr); }
            else        { LDSM_X4(bL[kp][0], bL[kp][1], bL[kp][2], bL[kp][3], addr); }
          }
        }
        __syncthreads();
      }
    }
  }

  const int hv_c   = nsl * 2 + ((lane & 3) >> 1);
  const int bl_c   = (lane >> 2) + ((lane & 1) ? 8 : 0);
  const int bglob  = bt * 16 + bl_c;
  const int hglob  = ht * 16 + hv_c;
  float4 bias4 = make_float4(0.f, 0.f, 0.f, 0.f);
  if (grp == 1) {
#pragma unroll
    for (int g = 0; g < 4; ++g) {
      int gc = g * 256 + ht * 16 + hv_c;
      ((float*)&bias4)[g] = b_ih[GH_ + gc] + b_hh[GH_ + gc];
    }
  }
  if (tid < 256) sC[(tid >> 4) * 17 + (tid & 15)] =
      c0[(size_t)(bt * 16 + (tid >> 4)) * H_ + ht * 16 + (tid & 15)];
  __syncthreads();

  float4 pv = make_float4(0.f, 0.f, 0.f, 0.f);
  if (grp == 0)
    pv = __ldcs((const float4*)&g_P[(size_t)bglob * GH_ + ht * 64 + hv_c * 4]);

  const int rA = lane & 15, eA = lane >> 4;
  const uint32_t aRow = sbase + OFF_A + rA * 512;
  // per-thread staging chunk (512 chunks per plane, 1 per thread)
  const int stR = tid >> 5, stC = tid & 31;
  const uint32_t stDstHi = sbase + OFF_A + stR * 512 + swz(stR, stC) * 16;
  const uint32_t stDstLo = stDstHi + 8192;
  const int stSrcOff = stR * 512 + stC * 16;

#pragma unroll 1
  for (int q = 0; q < 2 * S_; ++q) {
    const int t  = q >> 1;
    const int ph = q & 1;
    if (q) bar_wait(ctr, (unsigned)q * 16);

    // ---- stage A: hi commit-group then lo commit-group ----
    CP_ASYNC16(stDstHi, &g_img[ph][bt][0][stSrcOff]);
    CP_COMMIT();
    CP_ASYNC16(stDstLo, &g_img[ph][bt][1][stSrcOff]);
    CP_COMMIT();

    CP_WAIT(1);                 // hi plane (own chunk) done
    __syncthreads();            // all hi chunks visible CTA-wide

    float d[4] = {0.f, 0.f, 0.f, 0.f};
    float hval = 0.f, cnew = 0.f;
    if (grp == ph) {
      // ---- hi-fragment MMAs (32) while lo plane lands ----
#pragma unroll
      for (int kp = 0; kp < 8; ++kp) {
        uint32_t h0r, h1r, h2r, h3r, h4, h5, h6, h7;
        uint32_t a0 = aRow + swz(rA, 4 * kp + eA) * 16;
        uint32_t a1 = aRow + swz(rA, 4 * kp + 2 + eA) * 16;
        LDSM_X4(h0r, h1r, h2r, h3r, a0);
        LDSM_X4(h4, h5, h6, h7, a1);
        MMA_BF16(d, h0r, h1r, h2r, h3r, bH[kp][0], bH[kp][1]);
        MMA_BF16(d, h0r, h1r, h2r, h3r, bL[kp][0], bL[kp][1]);
        MMA_BF16(d, h4, h5, h6, h7,     bH[kp][2], bH[kp][3]);
        MMA_BF16(d, h4, h5, h6, h7,     bL[kp][2], bL[kp][3]);
      }
    }
    CP_WAIT(0);                 // lo plane (own chunk) done
    __syncthreads();            // all lo chunks visible CTA-wide

    if (grp == ph) {
#pragma unroll
      for (int kp = 0; kp < 8; ++kp) {
        uint32_t l0, l1, l2, l3, l4, l5, l6, l7;
        uint32_t a0 = aRow + swz(rA, 4 * kp + eA) * 16 + 8192;
        uint32_t a1 = aRow + swz(rA, 4 * kp + 2 + eA) * 16 + 8192;
        LDSM_X4(l0, l1, l2, l3, a0);
        LDSM_X4(l4, l5, l6, l7, a1);
        MMA_BF16(d, l0, l1, l2, l3, bH[kp][0], bH[kp][1]);
        MMA_BF16(d, l4, l5, l6, l7, bH[kp][2], bH[kp][3]);
      }
      // ---- register epilogue (validated) ----
      float e0 = __shfl_xor_sync(0xFFFFFFFFu, d[0], 1);
      float e1 = __shfl_xor_sync(0xFFFFFFFFu, d[1], 1);
      float e2 = __shfl_xor_sync(0xFFFFFFFFu, d[2], 1);
      float e3 = __shfl_xor_sync(0xFFFFFFFFu, d[3], 1);
      float gi, gf, gc, go;
      if (!(lane & 1)) { gi = d[0]; gf = d[1]; gc = e0; go = e1; }
      else             { gi = e2;   gf = e3;   gc = d[2]; go = d[3]; }
      float4 ab = (grp == 0) ? pv : bias4;
      gi += ab.x; gf += ab.y; gc += ab.z; go += ab.w;
      int ci = bl_c * 17 + hv_c;
      float cold = sC[ci];
      cnew = sigf(gf) * cold + sigf(gi) * fmaxf(gc, 0.0f);
      hval = sigf(go) * fmaxf(cnew, 0.0f);
      sC[ci] = cnew;
      __nv_bfloat16 hb = __float2bfloat16(hval);
      __nv_bfloat16 lb = __float2bfloat16(hval - __bfloat162float(hb));
      *(__nv_bfloat16*)&g_img[ph ^ 1][bt][0][bl_c * 512 + hglob * 2] = hb;
      *(__nv_bfloat16*)&g_img[ph ^ 1][bt][1][bl_c * 512 + hglob * 2] = lb;
      if (t == S_ - 1) {
        size_t lo2 = (size_t)ph * B_ * H_ + (size_t)bglob * H_ + hglob;
        out[HY_OFF + lo2] = hval;
        out[CY_OFF + lo2] = cnew;
      }
    }
    bar_arrive(ctr);
    // off-path work inside the barrier window
    if (grp == ph) {
      if (ph) __stcs(&out[(size_t)t * B_ * H_ + (size_t)bglob * H_ + hglob], hval);
    } else {
      if (grp == 0 && ph == 1 && t + 1 < S_)
        pv = __ldcs((const float4*)
                    &g_P[((size_t)(t + 1) * B_ + bglob) * GH_ + ht * 64 + hv_c * 4]);
    }
  }
}

extern "C" void kernel_launch(void* const* d_in, const int* in_sizes, int n_in,
                              void* d_out, int out_size) {
  const float* x    = (const float*)d_in[0];
  const float* h0   = (const float*)d_in[1];
  const float* c0   = (const float*)d_in[2];
  const float* w_ih = (const float*)d_in[3];
  const float* b_ih = (const float*)d_in[4];
  const float* w_hh = (const float*)d_in[5];
  const float* b_hh = (const float*)d_in[6];
  float* out = (float*)d_out;

  static bool attr_done = false;
  if (!attr_done) {
    cudaFuncSetAttribute(pro_main,
                         cudaFuncAttributeMaxDynamicSharedMemorySize, PRO_SMEM);
    cudaFuncSetAttribute(lstm_kernel,
                         cudaFuncAttributeMaxDynamicSharedMemorySize, LSTM_SMEM);
    attr_done = true;
  }

  setup_kernel<<<64, 256>>>(h0, w_ih);
  xconv_kernel<<<16384, 512>>>(x);
  pro_main<<<dim3(16, 9), 256, PRO_SMEM>>>(b_ih, b_hh);
  lstm_kernel<<<NCTA, NTHR, LSTM_SMEM>>>(c0, w_ih, b_ih, w_hh, b_hh, out);
}